// round 7
// baseline (speedup 1.0000x reference)
#include <cuda_runtime.h>
#include <cuda_bf16.h>
#include <math.h>
#include <cstdint>

#define NTOK 4096      // T*B
#define DDIM 1024
#define HDIM 2048
#define ODIM 1024
#define NEXP 8
#define EMAX 4096      // max tokens per expert

// int8 panel layout (A and B): per row, K grouped in 64-element chunks;
// chunk = [hi s8 x64 | lo s8 x64] = 128 bytes. Row stride = 2*Kd bytes.
// value ~= q * (128*hi + lo),  |15-bit| <= 16255.

// ---------------- scratch (device globals; no allocation allowed) ----------
__device__ float    g_xn[(size_t)NTOK * DDIM];                       // 16 MB
__device__ float    g_h [(size_t)NEXP * EMAX * HDIM];                // 268 MB f32 intermediate
__device__ float    g_y [(size_t)2 * NTOK * ODIM];                   // 32 MB
__device__ int      g_cnt[NEXP];
__device__ int      g_slots[NEXP * NTOK];
__device__ float    g_prob[2 * NTOK];
__device__ float    g_amax1[NTOK];                                   // per-token |xn| max
__device__ unsigned g_amax2u[NEXP * EMAX];                           // per-h-row |h| max (bits)
__device__ unsigned g_sbmax1u[NEXP * HDIM];                          // per-col |w1| max (bits)
__device__ unsigned g_sbmax2u[NEXP * ODIM];                          // per-col |w2| max (bits)
__device__ int8_t   g_A1[(size_t)NEXP * EMAX * (2 * DDIM)];          // 67 MB
__device__ int8_t   g_A2[(size_t)NEXP * EMAX * (2 * HDIM)];          // 134 MB
__device__ int8_t   g_B1[(size_t)NEXP * HDIM * (2 * DDIM)];          // 33.5 MB
__device__ int8_t   g_B2[(size_t)NEXP * ODIM * (2 * HDIM)];          // 33.5 MB

// ---------------- PTX helpers ----------------------------------------------
__device__ __forceinline__ uint32_t smem_to_u32(const void* p) {
    uint32_t a;
    asm("{ .reg .u64 t; cvta.to.shared.u64 t, %1; cvt.u32.u64 %0, t; }" : "=r"(a) : "l"(p));
    return a;
}
#define CP_ASYNC16(saddr, gptr) \
    asm volatile("cp.async.cg.shared.global [%0], [%1], 16;" :: "r"(saddr), "l"(gptr))
#define CP_COMMIT() asm volatile("cp.async.commit_group;" ::: "memory")
#define CP_WAIT1()  asm volatile("cp.async.wait_group 1;" ::: "memory")
#define LDSM_X4(R, addr) \
    asm volatile("ldmatrix.sync.aligned.m8n8.x4.shared.b16 {%0,%1,%2,%3}, [%4];" \
                 : "=r"((R)[0]), "=r"((R)[1]), "=r"((R)[2]), "=r"((R)[3]) : "r"(addr))
#define IMMA16832(D, A, B0, B1) \
    asm volatile("mma.sync.aligned.m16n8k32.row.col.s32.s8.s8.s32 " \
        "{%0,%1,%2,%3}, {%4,%5,%6,%7}, {%8,%9}, {%0,%1,%2,%3};" \
        : "+r"((D)[0]), "+r"((D)[1]), "+r"((D)[2]), "+r"((D)[3]) \
        : "r"((A)[0]), "r"((A)[1]), "r"((A)[2]), "r"((A)[3]), "r"(B0), "r"(B1))

__device__ __forceinline__ float gelu_exact(float v) {
    return 0.5f * v * (1.0f + erff(v * 0.70710678118654752440f));
}
// quantize to 15-bit, split into hi (x128) + lo
__device__ __forceinline__ void q15(float v, float q, int8_t& hi, int8_t& lo) {
    float f = fminf(fmaxf(v * q, -16255.f), 16255.f);
    int a = __float2int_rn(f);
    int h = (a + 64) >> 7;
    hi = (int8_t)h;
    lo = (int8_t)(a - (h << 7));
}

// ---------------- kernel 0: zero counters / max accumulators ---------------
__global__ void zero_kernel() {
    int idx = blockIdx.x * 256 + threadIdx.x;
    if (idx < NEXP * EMAX) g_amax2u[idx] = 0u;
    if (idx < NEXP * HDIM) g_sbmax1u[idx] = 0u;
    if (idx < NEXP * ODIM) g_sbmax2u[idx] = 0u;
    if (idx < NEXP) g_cnt[idx] = 0;
}

// ---------------- kernel 1: LN + router + top2 + scatter + amax ------------
__global__ __launch_bounds__(256)
void ln_router_kernel(const float* __restrict__ x,
                      const float* __restrict__ gamma,
                      const float* __restrict__ beta,
                      const float* __restrict__ rw,
                      float* __restrict__ logits_out,
                      int write_logits)
{
    const int n = blockIdx.x;
    const int tid = threadIdx.x;
    __shared__ float sx[DDIM];
    __shared__ float red[256];
    __shared__ float sstat[2];
    __shared__ float lg[NEXP];

    const float* xr = x + (size_t)n * DDIM;
    float s = 0.f;
    for (int i = tid; i < DDIM; i += 256) { float v = xr[i]; sx[i] = v; s += v; }
    red[tid] = s; __syncthreads();
    for (int st = 128; st > 0; st >>= 1) { if (tid < st) red[tid] += red[tid + st]; __syncthreads(); }
    if (tid == 0) sstat[0] = red[0] * (1.0f / DDIM);
    __syncthreads();
    const float mu = sstat[0];
    float s2 = 0.f;
    for (int i = tid; i < DDIM; i += 256) { float v = sx[i] - mu; s2 += v * v; }
    red[tid] = s2; __syncthreads();
    for (int st = 128; st > 0; st >>= 1) { if (tid < st) red[tid] += red[tid + st]; __syncthreads(); }
    if (tid == 0) sstat[1] = rsqrtf(red[0] * (1.0f / DDIM) + 1e-5f);
    __syncthreads();
    const float rstd = sstat[1];
    float am = 0.f;
    for (int i = tid; i < DDIM; i += 256) {
        float v = (sx[i] - mu) * rstd * gamma[i] + beta[i];
        sx[i] = v;
        am = fmaxf(am, fabsf(v));
        g_xn[(size_t)n * DDIM + i] = v;
    }
    red[tid] = am; __syncthreads();
    for (int st = 128; st > 0; st >>= 1) { if (tid < st) red[tid] = fmaxf(red[tid], red[tid + st]); __syncthreads(); }
    if (tid == 0) g_amax1[n] = fmaxf(red[0], 1e-12f);
    __syncthreads();

    const int w = tid >> 5, lane = tid & 31;
    {
        const float* r = rw + w * DDIM;
        float p = 0.f;
        for (int i = lane; i < DDIM; i += 32) p += sx[i] * r[i];
        #pragma unroll
        for (int o = 16; o > 0; o >>= 1) p += __shfl_down_sync(0xffffffffu, p, o);
        if (lane == 0) lg[w] = p;
    }
    __syncthreads();

    if (tid == 0) {
        if (write_logits) {
            #pragma unroll
            for (int e = 0; e < NEXP; e++) logits_out[(size_t)n * NEXP + e] = lg[e];
        }
        int i0 = 0;
        #pragma unroll
        for (int e = 1; e < NEXP; e++) if (lg[e] > lg[i0]) i0 = e;
        int i1 = (i0 == 0) ? 1 : 0;
        #pragma unroll
        for (int e = 0; e < NEXP; e++) if (e != i0 && lg[e] > lg[i1]) i1 = e;
        float q = expf(lg[i1] - lg[i0]);
        float inv = 1.0f / (1.0f + q);
        g_prob[2 * n]     = inv;
        g_prob[2 * n + 1] = q * inv;
        int p0 = atomicAdd(&g_cnt[i0], 1); g_slots[i0 * NTOK + p0] = 2 * n;
        int p1 = atomicAdd(&g_cnt[i1], 1); g_slots[i1 * NTOK + p1] = 2 * n + 1;
    }
}

// ---------------- kernel 2: pack + quantize tokens into A1 -----------------
__global__ __launch_bounds__(256)
void pack1_kernel()
{
    const int e = blockIdx.y;
    const int m0 = blockIdx.x * 128;
    const int cnt = g_cnt[e];
    if (m0 >= cnt) return;
    const int tid = threadIdx.x;
    int8_t* outp = g_A1 + ((size_t)e * EMAX) * (2 * DDIM);
    for (int idx = tid; idx < 128 * 256; idx += 256) {
        int r = idx >> 8;
        int c4 = idx & 255;
        int row = m0 + r;
        if (row >= cnt) continue;
        int token = g_slots[e * NTOK + row] >> 1;
        float q = 16255.f / g_amax1[token];
        float4 v = ((const float4*)g_xn)[(size_t)token * 256 + c4];
        int c = c4 * 4;
        int ch = c >> 6, pos = c & 63;
        union { int8_t b[4]; uint32_t u; } hv, lv;
        q15(v.x, q, hv.b[0], lv.b[0]);
        q15(v.y, q, hv.b[1], lv.b[1]);
        q15(v.z, q, hv.b[2], lv.b[2]);
        q15(v.w, q, hv.b[3], lv.b[3]);
        int8_t* rb = outp + (size_t)row * (2 * DDIM) + ch * 128 + pos;
        *(uint32_t*)rb = hv.u;
        *(uint32_t*)(rb + 64) = lv.u;
    }
}

// ---------------- kernel 3a: per-column weight amax ------------------------
template<int LAYER>
__global__ __launch_bounds__(256)
void colmax_kernel(const float* __restrict__ W)
{
    constexpr int Kd = (LAYER == 1) ? DDIM : HDIM;
    constexpr int Nd = (LAYER == 1) ? HDIM : ODIM;
    unsigned* outp = (LAYER == 1) ? g_sbmax1u : g_sbmax2u;
    const int e = blockIdx.z;
    const int col = blockIdx.x * 256 + threadIdx.x;
    const int k0 = blockIdx.y * (Kd / 8);
    const float* base = W + ((size_t)e * Kd + k0) * Nd + col;
    float m = 0.f;
    #pragma unroll 4
    for (int k = 0; k < Kd / 8; k++) m = fmaxf(m, fabsf(base[(size_t)k * Nd]));
    atomicMax(&outp[e * Nd + col], __float_as_uint(m));
}

// ---------------- kernel 3b: weight transpose + int8 split -----------------
// W [E][Kd][Nd] f32 -> B [E][Nd][chunk hi|lo] int8
template<int LAYER>
__global__ __launch_bounds__(256)
void wquant_kernel(const float* __restrict__ W)
{
    constexpr int Kd = (LAYER == 1) ? DDIM : HDIM;
    constexpr int Nd = (LAYER == 1) ? HDIM : ODIM;
    int8_t* Bout = (LAYER == 1) ? g_B1 : g_B2;
    const unsigned* smax = (LAYER == 1) ? g_sbmax1u : g_sbmax2u;
    const int e = blockIdx.z;
    const int k0 = blockIdx.x * 64;   // one 64-chunk
    const int n0 = blockIdx.y * 32;
    __shared__ float sw_[64][33];
    const int tid = threadIdx.x;
    {
        int r = tid >> 2, cq = tid & 3;
        const float* src = W + ((size_t)e * Kd + k0 + r) * Nd + n0 + cq * 8;
        float4 v0 = *(const float4*)src;
        float4 v1 = *(const float4*)(src + 4);
        sw_[r][cq * 8 + 0] = v0.x; sw_[r][cq * 8 + 1] = v0.y;
        sw_[r][cq * 8 + 2] = v0.z; sw_[r][cq * 8 + 3] = v0.w;
        sw_[r][cq * 8 + 4] = v1.x; sw_[r][cq * 8 + 5] = v1.y;
        sw_[r][cq * 8 + 6] = v1.z; sw_[r][cq * 8 + 7] = v1.w;
    }
    __syncthreads();
    const int n = tid >> 3, s = tid & 7;
    const float q = 16255.f / fmaxf(__uint_as_float(smax[e * Nd + n0 + n]), 1e-12f);
    union { int8_t b[8]; uint2 u; } hv, lv;
    #pragma unroll
    for (int j = 0; j < 8; j++) q15(sw_[s * 8 + j][n], q, hv.b[j], lv.b[j]);
    int8_t* dst = Bout + ((size_t)e * Nd + n0 + n) * (2 * Kd) + blockIdx.x * 128 + s * 8;
    *(uint2*)dst = hv.u;
    *(uint2*)(dst + 64) = lv.u;
}

// ---------------- kernels 4/6: grouped int8 GEMM via mma.sync --------------
// Tile 128x128; chunk = 64 K = [hi 64B | lo 64B]. Accumulate:
//   Chh (hi*hi) and Cx (hi*lo + lo*hi);  value = qA*qB*(16384*Chh + 128*Cx)
template<int LAYER>
__global__ __launch_bounds__(256, 1)
void mma_gemm(const float* __restrict__ bias_all)
{
    constexpr int Kd = (LAYER == 1) ? DDIM : HDIM;
    constexpr int Nd = (LAYER == 1) ? HDIM : ODIM;
    constexpr int NCH = Kd / 64;
    constexpr int STAGE_BYTES = 32768;   // A 16K + B 16K
    const int8_t* __restrict__ Aall = (LAYER == 1) ? g_A1 : g_A2;
    const int8_t* __restrict__ Ball = (LAYER == 1) ? g_B1 : g_B2;
    const unsigned* smax = (LAYER == 1) ? g_sbmax1u : g_sbmax2u;

    const int e = blockIdx.z;
    const int cnt = g_cnt[e];
    const int m0 = blockIdx.x * 128;
    if (m0 >= cnt) return;
    const int n0 = blockIdx.y * 128;

    extern __shared__ __align__(1024) char smem[];
    const uint32_t smem_u = smem_to_u32(smem);
    __shared__ float sbias[128];
    __shared__ float sqb[128];

    const int tid = threadIdx.x;
    const int lane = tid & 31;
    const int wid = tid >> 5;
    const int wm = wid >> 1;
    const int wn = wid & 1;

    if (tid < 128) {
        sbias[tid] = bias_all[(size_t)e * Nd + n0 + tid];
        sqb[tid] = __uint_as_float(smax[e * Nd + n0 + tid]) * (1.f / 16255.f);
    }

    const size_t rstride = 2 * Kd;  // bytes
    const int8_t* Abase = Aall + ((size_t)e * EMAX + m0) * rstride;
    const int8_t* Bbase = Ball + ((size_t)e * Nd + n0) * rstride;

    const int lr = tid >> 3;          // 4 rows/thread, stride 32
    const int lch = tid & 7;
    const uint32_t lsw = (uint32_t)(lch * 16) ^ (uint32_t)((lr & 7) << 4);

    int acch[2][8][4], accx[2][8][4];
    #pragma unroll
    for (int i = 0; i < 2; i++)
        #pragma unroll
        for (int j = 0; j < 8; j++)
            #pragma unroll
            for (int q = 0; q < 4; q++) { acch[i][j][q] = 0; accx[i][j][q] = 0; }

    auto load_stage = [&](int c, int st) {
        const int col = c * 128;      // byte offset of chunk
        const uint32_t sA = smem_u + st * STAGE_BYTES;
        const uint32_t sB = sA + 16384;
        #pragma unroll
        for (int l = 0; l < 4; l++) {
            int r = lr + l * 32;
            CP_ASYNC16(sA + (uint32_t)(r * 128) + lsw,
                       Abase + (size_t)r * rstride + col + lch * 16);
        }
        #pragma unroll
        for (int l = 0; l < 4; l++) {
            int r = lr + l * 32;
            CP_ASYNC16(sB + (uint32_t)(r * 128) + lsw,
                       Bbase + (size_t)r * rstride + col + lch * 16);
        }
    };

    const int rowA0 = wm * 32 + (lane & 15);
    const int kbA = (lane >> 4) * 16;           // byte offset
    const int g = lane >> 3;
    const int rowB0 = wn * 64 + ((g >> 1) << 3) + (lane & 7);
    const int kbB = (g & 1) * 16;               // byte offset

    auto compute_stage = [&](int st) {
        const uint32_t sA = smem_u + st * STAGE_BYTES;
        const uint32_t sB = sA + 16384;
        #pragma unroll
        for (int c2 = 0; c2 < 2; c2++) {
            uint32_t ah[2][4], al[2][4];
            #pragma unroll
            for (int mf = 0; mf < 2; mf++) {
                int row = rowA0 + mf * 16;
                uint32_t base = sA + (uint32_t)(row * 128);
                uint32_t sw = (uint32_t)((row & 7) << 4);
                uint32_t kh = (uint32_t)(c2 * 32 + kbA);
                LDSM_X4(ah[mf], base + (kh ^ sw));
                LDSM_X4(al[mf], base + ((kh + 64) ^ sw));
            }
            #pragma unroll
            for (int ng = 0; ng < 4; ng++) {
                int row = rowB0 + ng * 16;
                uint32_t base = sB + (uint32_t)(row * 128);
                uint32_t sw = (uint32_t)((row & 7) << 4);
                uint32_t kh = (uint32_t)(c2 * 32 + kbB);
                uint32_t bh[4], bl[4];
                LDSM_X4(bh, base + (kh ^ sw));
                LDSM_X4(bl, base + ((kh + 64) ^ sw));
                #pragma unroll
                for (int mf = 0; mf < 2; mf++) {
                    IMMA16832(acch[mf][2 * ng],     ah[mf], bh[0], bh[1]);
                    IMMA16832(acch[mf][2 * ng + 1], ah[mf], bh[2], bh[3]);
                    IMMA16832(accx[mf][2 * ng],     ah[mf], bl[0], bl[1]);
                    IMMA16832(accx[mf][2 * ng + 1], ah[mf], bl[2], bl[3]);
                    IMMA16832(accx[mf][2 * ng],     al[mf], bh[0], bh[1]);
                    IMMA16832(accx[mf][2 * ng + 1], al[mf], bh[2], bh[3]);
                }
            }
        }
    };

    load_stage(0, 0); CP_COMMIT();
    load_stage(1, 1); CP_COMMIT();
    for (int c = 0; c < NCH; c++) {
        CP_WAIT1();
        __syncthreads();
        if (c + 2 < NCH) load_stage(c + 2, (c + 2) % 3);
        CP_COMMIT();
        compute_stage(c % 3);
    }

    // ---------------- epilogue --------------------------------------------
    const int rbase = m0 + wm * 32 + (lane >> 2);
    const int cbase = wn * 64 + (lane & 3) * 2;   // local col in tile

    #pragma unroll
    for (int mf = 0; mf < 2; mf++) {
        #pragma unroll
        for (int cp = 0; cp < 2; cp++) {
            int row = rbase + mf * 16 + cp * 8;
            if (row >= cnt) continue;
            float qa;
            if (LAYER == 1) qa = g_amax1[g_slots[e * NTOK + row] >> 1] * (1.f / 16255.f);
            else            qa = __uint_as_float(g_amax2u[e * EMAX + row]) * (1.f / 16255.f);
            if (LAYER == 1) {
                float* orow = g_h + ((size_t)e * EMAX + row) * HDIM + n0;
                float lm = 0.f;
                #pragma unroll
                for (int nf = 0; nf < 8; nf++) {
                    int col = cbase + nf * 8;
                    float d0 = 16384.f * (float)acch[mf][nf][2 * cp]     + 128.f * (float)accx[mf][nf][2 * cp];
                    float d1 = 16384.f * (float)acch[mf][nf][2 * cp + 1] + 128.f * (float)accx[mf][nf][2 * cp + 1];
                    float v0 = gelu_exact(d0 * qa * sqb[col]     + sbias[col]);
                    float v1 = gelu_exact(d1 * qa * sqb[col + 1] + sbias[col + 1]);
                    lm = fmaxf(lm, fmaxf(fabsf(v0), fabsf(v1)));
                    *(float2*)&orow[col] = make_float2(v0, v1);
                }
                atomicMax(&g_amax2u[e * EMAX + row], __float_as_uint(lm));
            } else {
                int slot = g_slots[e * NTOK + row];
                float* orow = g_y + (size_t)slot * ODIM + n0;
                #pragma unroll
                for (int nf = 0; nf < 8; nf++) {
                    int col = cbase + nf * 8;
                    float d0 = 16384.f * (float)acch[mf][nf][2 * cp]     + 128.f * (float)accx[mf][nf][2 * cp];
                    float d1 = 16384.f * (float)acch[mf][nf][2 * cp + 1] + 128.f * (float)accx[mf][nf][2 * cp + 1];
                    float v0 = gelu_exact(d0 * qa * sqb[col]     + sbias[col]);
                    float v1 = gelu_exact(d1 * qa * sqb[col + 1] + sbias[col + 1]);
                    *(float2*)&orow[col] = make_float2(v0, v1);
                }
            }
        }
    }
}

// ---------------- kernel 5: quantize h -> A2 panels ------------------------
__global__ __launch_bounds__(256)
void quant2_kernel()
{
    const int e = blockIdx.y;
    const int cnt = g_cnt[e];
    const int r0 = blockIdx.x * 8;
    if (r0 >= cnt) return;
    const int tid = threadIdx.x;
    const int r = r0 + (tid >> 5);
    if (r >= cnt) return;
    const int lane = tid & 31;
    const float q = 16255.f / fmaxf(__uint_as_float(g_amax2u[e * EMAX + r]), 1e-12f);
    const float* hrow = g_h + ((size_t)e * EMAX + r) * HDIM;
    int8_t* arow = g_A2 + ((size_t)e * EMAX + r) * (2 * HDIM);
    #pragma unroll
    for (int it = 0; it < 4; it++) {
        int k = lane * 16 + it * 512;
        union { int8_t b[16]; uint4 u; } hv, lv;
        #pragma unroll
        for (int j = 0; j < 16; j += 4) {
            float4 v = *(const float4*)(hrow + k + j);
            q15(v.x, q, hv.b[j],     lv.b[j]);
            q15(v.y, q, hv.b[j + 1], lv.b[j + 1]);
            q15(v.z, q, hv.b[j + 2], lv.b[j + 2]);
            q15(v.w, q, hv.b[j + 3], lv.b[j + 3]);
        }
        int ch = k >> 6, pos = k & 63;
        int8_t* dst = arow + ch * 128 + pos;
        *(uint4*)dst = hv.u;
        *(uint4*)(dst + 64) = lv.u;
    }
}

// ---------------- kernel 7: combine + mask ---------------------------------
__global__ __launch_bounds__(256)
void combine_kernel(const float* __restrict__ mask, float* __restrict__ out)
{
    const int n = blockIdx.x;
    const int tid = threadIdx.x;
    const float m  = mask[n];
    const float p0 = g_prob[2 * n] * m;
    const float p1 = g_prob[2 * n + 1] * m;
    const float* y0 = g_y + (size_t)(2 * n) * ODIM;
    const float* y1 = y0 + ODIM;
    float* o = out + (size_t)n * ODIM;
    for (int c = tid; c < ODIM; c += 256)
        o[c] = p0 * y0[c] + p1 * y1[c];
}

// ---------------- launch ----------------------------------------------------
extern "C" void kernel_launch(void* const* d_in, const int* in_sizes, int n_in,
                              void* d_out, int out_size)
{
    const float* x     = (const float*)d_in[0];
    const float* mask  = (const float*)d_in[1];
    const float* gamma = (const float*)d_in[2];
    const float* beta  = (const float*)d_in[3];
    const float* rw    = (const float*)d_in[4];
    const float* w1    = (const float*)d_in[5];
    const float* b1    = (const float*)d_in[6];
    const float* w2    = (const float*)d_in[7];
    const float* b2    = (const float*)d_in[8];
    float* out = (float*)d_out;

    const int TBO = NTOK * ODIM;
    const int write_logits = (out_size >= TBO + NTOK * NEXP) ? 1 : 0;
    const int DSMEM = 98304;   // 3 stages x (16K A + 16K B)

    static int attr_done = 0;
    if (!attr_done) {
        cudaFuncSetAttribute(mma_gemm<1>, cudaFuncAttributeMaxDynamicSharedMemorySize, DSMEM);
        cudaFuncSetAttribute(mma_gemm<2>, cudaFuncAttributeMaxDynamicSharedMemorySize, DSMEM);
        attr_done = 1;
    }

    zero_kernel<<<128, 256>>>();
    ln_router_kernel<<<NTOK, 256>>>(x, gamma, beta, rw, out + TBO, write_logits);
    pack1_kernel<<<dim3(EMAX / 128, NEXP), 256>>>();
    colmax_kernel<1><<<dim3(HDIM / 256, 8, NEXP), 256>>>(w1);
    colmax_kernel<2><<<dim3(ODIM / 256, 8, NEXP), 256>>>(w2);
    wquant_kernel<1><<<dim3(DDIM / 64, HDIM / 32, NEXP), 256>>>(w1);
    wquant_kernel<2><<<dim3(HDIM / 64, ODIM / 32, NEXP), 256>>>(w2);
    mma_gemm<1><<<dim3(EMAX / 128, HDIM / 128, NEXP), 256, DSMEM>>>(b1);
    quant2_kernel<<<dim3(EMAX / 8, NEXP), 256>>>();
    mma_gemm<2><<<dim3(EMAX / 128, ODIM / 128, NEXP), 256, DSMEM>>>(b2);
    combine_kernel<<<NTOK, 256>>>(mask, out);
}

// round 9
// speedup vs baseline: 2.7807x; 2.7807x over previous
#include <cuda_runtime.h>
#include <cuda_bf16.h>
#include <math.h>
#include <cstdint>

#define NTOK 4096      // T*B
#define DDIM 1024
#define HDIM 2048
#define ODIM 1024
#define NEXP 8
#define EMAX 4096      // max tokens per expert

// Panel layout (A and B): per row, K grouped in 32-element chunks, each chunk
// stored as 64 consecutive bf16 = [hi 0..31 | lo 0..31] (128 bytes).
// Row stride = 2*Kd elements.

// ---------------- scratch (device globals; no allocation allowed) ----------
__device__ float g_xn[(size_t)NTOK * DDIM];                          // 16 MB
__device__ float g_y[(size_t)2 * NTOK * ODIM];                       // 32 MB
__device__ int   g_cnt[NEXP];
__device__ int   g_slots[NEXP * NTOK];
__device__ float g_prob[2 * NTOK];
__device__ __nv_bfloat16 g_A1[(size_t)NEXP * EMAX * (2 * DDIM)];     // 134 MB
__device__ __nv_bfloat16 g_A2[(size_t)NEXP * EMAX * (2 * HDIM)];     // 268 MB
__device__ __nv_bfloat16 g_B1[(size_t)NEXP * HDIM * (2 * DDIM)];     // 67 MB
__device__ __nv_bfloat16 g_B2[(size_t)NEXP * ODIM * (2 * HDIM)];     // 67 MB

// ---------------- PTX helpers ----------------------------------------------
__device__ __forceinline__ uint32_t smem_to_u32(const void* p) {
    uint32_t a;
    asm("{ .reg .u64 t; cvta.to.shared.u64 t, %1; cvt.u32.u64 %0, t; }" : "=r"(a) : "l"(p));
    return a;
}
#define CP_ASYNC16(saddr, gptr) \
    asm volatile("cp.async.cg.shared.global [%0], [%1], 16;" :: "r"(saddr), "l"(gptr))
#define CP_COMMIT() asm volatile("cp.async.commit_group;" ::: "memory")
#define CP_WAIT1()  asm volatile("cp.async.wait_group 1;" ::: "memory")
#define LDSM_X4(R, addr) \
    asm volatile("ldmatrix.sync.aligned.m8n8.x4.shared.b16 {%0,%1,%2,%3}, [%4];" \
                 : "=r"((R)[0]), "=r"((R)[1]), "=r"((R)[2]), "=r"((R)[3]) : "r"(addr))
#define MMA16816(D, A, B0, B1) \
    asm volatile("mma.sync.aligned.m16n8k16.row.col.f32.bf16.bf16.f32 " \
        "{%0,%1,%2,%3}, {%4,%5,%6,%7}, {%8,%9}, {%0,%1,%2,%3};" \
        : "+f"((D)[0]), "+f"((D)[1]), "+f"((D)[2]), "+f"((D)[3]) \
        : "r"((A)[0]), "r"((A)[1]), "r"((A)[2]), "r"((A)[3]), "r"(B0), "r"(B1))

__device__ __forceinline__ float gelu_exact(float v) {
    return 0.5f * v * (1.0f + erff(v * 0.70710678118654752440f));
}
__device__ __forceinline__ uint32_t pack_hi2(float a, float b) {
    __nv_bfloat16 ha = __float2bfloat16(a), hb = __float2bfloat16(b);
    return (uint32_t)*(uint16_t*)&ha | ((uint32_t)*(uint16_t*)&hb << 16);
}
__device__ __forceinline__ uint32_t pack_lo2(float a, float b) {
    __nv_bfloat16 ha = __float2bfloat16(a), hb = __float2bfloat16(b);
    __nv_bfloat16 la = __float2bfloat16(a - __bfloat162float(ha));
    __nv_bfloat16 lb = __float2bfloat16(b - __bfloat162float(hb));
    return (uint32_t)*(uint16_t*)&la | ((uint32_t)*(uint16_t*)&lb << 16);
}

// ---------------- kernel 0: zero counters ----------------------------------
__global__ void zero_kernel() {
    if (threadIdx.x < NEXP) g_cnt[threadIdx.x] = 0;
}

// ---------------- kernel 1: LN + router + top2 + scatter -------------------
__global__ __launch_bounds__(256)
void ln_router_kernel(const float* __restrict__ x,
                      const float* __restrict__ gamma,
                      const float* __restrict__ beta,
                      const float* __restrict__ rw,
                      float* __restrict__ logits_out,
                      int write_logits)
{
    const int n = blockIdx.x;
    const int tid = threadIdx.x;
    __shared__ float sx[DDIM];
    __shared__ float red[256];
    __shared__ float sstat[2];
    __shared__ float lg[NEXP];

    const float* xr = x + (size_t)n * DDIM;
    float s = 0.f;
    for (int i = tid; i < DDIM; i += 256) { float v = xr[i]; sx[i] = v; s += v; }
    red[tid] = s; __syncthreads();
    for (int st = 128; st > 0; st >>= 1) { if (tid < st) red[tid] += red[tid + st]; __syncthreads(); }
    if (tid == 0) sstat[0] = red[0] * (1.0f / DDIM);
    __syncthreads();
    const float mu = sstat[0];
    float s2 = 0.f;
    for (int i = tid; i < DDIM; i += 256) { float v = sx[i] - mu; s2 += v * v; }
    red[tid] = s2; __syncthreads();
    for (int st = 128; st > 0; st >>= 1) { if (tid < st) red[tid] += red[tid + st]; __syncthreads(); }
    if (tid == 0) sstat[1] = rsqrtf(red[0] * (1.0f / DDIM) + 1e-5f);
    __syncthreads();
    const float rstd = sstat[1];
    for (int i = tid; i < DDIM; i += 256) {
        float v = (sx[i] - mu) * rstd * gamma[i] + beta[i];
        sx[i] = v;
        g_xn[(size_t)n * DDIM + i] = v;
    }
    __syncthreads();

    const int w = tid >> 5, lane = tid & 31;
    {
        const float* r = rw + w * DDIM;
        float p = 0.f;
        for (int i = lane; i < DDIM; i += 32) p += sx[i] * r[i];
        #pragma unroll
        for (int o = 16; o > 0; o >>= 1) p += __shfl_down_sync(0xffffffffu, p, o);
        if (lane == 0) lg[w] = p;
    }
    __syncthreads();

    if (tid == 0) {
        if (write_logits) {
            #pragma unroll
            for (int e = 0; e < NEXP; e++) logits_out[(size_t)n * NEXP + e] = lg[e];
        }
        int i0 = 0;
        #pragma unroll
        for (int e = 1; e < NEXP; e++) if (lg[e] > lg[i0]) i0 = e;
        int i1 = (i0 == 0) ? 1 : 0;
        #pragma unroll
        for (int e = 0; e < NEXP; e++) if (e != i0 && lg[e] > lg[i1]) i1 = e;
        float q = expf(lg[i1] - lg[i0]);
        float inv = 1.0f / (1.0f + q);
        g_prob[2 * n]     = inv;
        g_prob[2 * n + 1] = q * inv;
        int p0 = atomicAdd(&g_cnt[i0], 1); g_slots[i0 * NTOK + p0] = 2 * n;
        int p1 = atomicAdd(&g_cnt[i1], 1); g_slots[i1 * NTOK + p1] = 2 * n + 1;
    }
}

// ---------------- kernel 2: pack tokens into per-expert A1 -----------------
__global__ __launch_bounds__(256)
void pack1_kernel()
{
    const int e = blockIdx.y;
    const int m0 = blockIdx.x * 128;
    const int cnt = g_cnt[e];
    if (m0 >= cnt) return;
    const int tid = threadIdx.x;
    __nv_bfloat16* outp = g_A1 + ((size_t)e * EMAX) * (2 * DDIM);
    for (int idx = tid; idx < 128 * 256; idx += 256) {
        int r = idx >> 8;
        int c4 = idx & 255;
        int row = m0 + r;
        if (row >= cnt) continue;
        int token = g_slots[e * NTOK + row] >> 1;
        float4 v = ((const float4*)g_xn)[(size_t)token * 256 + c4];
        size_t rb = (size_t)row * (2 * DDIM);
        int c = c4 * 4;               // k index, multiple of 4
        int ch = c >> 5, pos = c & 31;
        uint2 hp = make_uint2(pack_hi2(v.x, v.y), pack_hi2(v.z, v.w));
        uint2 lp = make_uint2(pack_lo2(v.x, v.y), pack_lo2(v.z, v.w));
        *(uint2*)&outp[rb + ch * 64 + pos]      = hp;
        *(uint2*)&outp[rb + ch * 64 + pos + 32] = lp;
    }
}

// ---------------- kernel 3: weight transpose + hi/lo split -----------------
// W [E][Kd][Nd] (fp32) -> B [E][Nd][chunked hi|lo] (bf16)
template<int LAYER>
__global__ __launch_bounds__(256)
void wcvt_kernel(const float* __restrict__ W)
{
    constexpr int Kd = (LAYER == 1) ? DDIM : HDIM;
    constexpr int Nd = (LAYER == 1) ? HDIM : ODIM;
    __nv_bfloat16* Bout = (LAYER == 1) ? g_B1 : g_B2;
    const int e = blockIdx.z;
    const int d0 = blockIdx.x * 32;   // K chunk base
    const int h0 = blockIdx.y * 32;   // N base
    __shared__ float st[32][33];
    const int tid = threadIdx.x;
    {
        int dl = tid >> 3, q = tid & 7;
        float4 v = *(const float4*)(W + ((size_t)e * Kd + d0 + dl) * Nd + h0 + q * 4);
        st[dl][q * 4 + 0] = v.x; st[dl][q * 4 + 1] = v.y;
        st[dl][q * 4 + 2] = v.z; st[dl][q * 4 + 3] = v.w;
    }
    __syncthreads();
    const int n = tid >> 3, seg = tid & 7;
    const int isLo = seg >> 2, j0 = (seg & 3) * 8;
    uint32_t pk[4];
    #pragma unroll
    for (int q = 0; q < 4; q++) {
        float a = st[j0 + 2 * q][n], b = st[j0 + 2 * q + 1][n];
        pk[q] = isLo ? pack_lo2(a, b) : pack_hi2(a, b);
    }
    size_t rb = ((size_t)e * Nd + h0 + n) * (size_t)(2 * Kd);
    int off = (d0 >> 5) * 64 + isLo * 32 + j0;
    *(uint4*)&Bout[rb + off] = *(uint4*)pk;
}

// ---------------- kernels 4/5: grouped bf16x3 GEMM via mma.sync ------------
// Tile 128x128; chunk = 32 K (hi+lo in one 128B row). 3-stage cp.async.
// Pass-major MMA schedule: per k16-step, all 16 hh MMAs, then 16 lh, then 16 hl
// (accumulator reuse distance = 16 -> HMMA RAW chains fully hidden).
template<int LAYER>
__global__ __launch_bounds__(256, 2)
void mma_gemm(const float* __restrict__ bias_all)
{
    constexpr int Kd = (LAYER == 1) ? DDIM : HDIM;
    constexpr int Nd = (LAYER == 1) ? HDIM : ODIM;
    constexpr int NCH = Kd / 32;
    constexpr int STAGE_BYTES = 32768;   // A 16K + B 16K
    const __nv_bfloat16* __restrict__ Aall = (LAYER == 1) ? g_A1 : g_A2;
    const __nv_bfloat16* __restrict__ Ball = (LAYER == 1) ? g_B1 : g_B2;

    const int e = blockIdx.z;
    const int cnt = g_cnt[e];
    const int m0 = blockIdx.x * 128;
    if (m0 >= cnt) return;
    const int n0 = blockIdx.y * 128;

    extern __shared__ __align__(1024) char smem[];
    const uint32_t smem_u = smem_to_u32(smem);

    const int tid = threadIdx.x;
    const int lane = tid & 31;
    const int wid = tid >> 5;
    const int wm = wid >> 1;
    const int wn = wid & 1;

    const size_t rstride = 2 * Kd;
    const __nv_bfloat16* Abase = Aall + ((size_t)e * EMAX + m0) * rstride;
    const __nv_bfloat16* Bbase = Ball + ((size_t)e * Nd + n0) * rstride;

    const int lr = tid >> 3;          // 4 rows/thread, stride 32
    const int lch = tid & 7;          // 16B chunk in 128B row
    const uint32_t lsw = (uint32_t)(lch * 16) ^ (uint32_t)((lr & 7) << 4);

    float acc[2][8][4];
    #pragma unroll
    for (int i = 0; i < 2; i++)
        #pragma unroll
        for (int j = 0; j < 8; j++)
            #pragma unroll
            for (int q = 0; q < 4; q++) acc[i][j][q] = 0.f;

    auto load_stage = [&](int c, int st) {
        const int col = c * 64;       // element offset of chunk (hi|lo 128B)
        const uint32_t sA = smem_u + st * STAGE_BYTES;
        const uint32_t sB = sA + 16384;
        #pragma unroll
        for (int l = 0; l < 4; l++) {
            int r = lr + l * 32;
            CP_ASYNC16(sA + (uint32_t)(r * 128) + lsw,
                       (const char*)(Abase + (size_t)r * rstride + col) + lch * 16);
        }
        #pragma unroll
        for (int l = 0; l < 4; l++) {
            int r = lr + l * 32;
            CP_ASYNC16(sB + (uint32_t)(r * 128) + lsw,
                       (const char*)(Bbase + (size_t)r * rstride + col) + lch * 16);
        }
    };

    const int rowA0 = wm * 32 + (lane & 15);
    const int kbA = (lane >> 4) * 8;
    const int g = lane >> 3;
    const int rowB0 = wn * 64 + ((g >> 1) << 3) + (lane & 7);
    const int kbB = (g & 1) * 8;

    auto compute_stage = [&](int st) {
        const uint32_t sA = smem_u + st * STAGE_BYTES;
        const uint32_t sB = sA + 16384;
        #pragma unroll
        for (int ks = 0; ks < 2; ks++) {
            uint32_t ah[2][4], al[2][4], bf[4][4];
            #pragma unroll
            for (int mf = 0; mf < 2; mf++) {
                int row = rowA0 + mf * 16;
                uint32_t base = sA + (uint32_t)(row * 128);
                uint32_t sw = (uint32_t)((row & 7) << 4);
                uint32_t kh = (uint32_t)((ks * 16 + kbA) * 2);
                LDSM_X4(ah[mf], base + (kh ^ sw));
                LDSM_X4(al[mf], base + ((kh + 64) ^ sw));
            }
            // load B hi for all ng
            #pragma unroll
            for (int ng = 0; ng < 4; ng++) {
                int row = rowB0 + ng * 16;
                uint32_t base = sB + (uint32_t)(row * 128);
                uint32_t sw = (uint32_t)((row & 7) << 4);
                uint32_t kh = (uint32_t)((ks * 16 + kbB) * 2);
                LDSM_X4(bf[ng], base + (kh ^ sw));
            }
            // pass 1: Ahi * Bhi  (16 MMAs, all-distinct accumulators)
            #pragma unroll
            for (int ng = 0; ng < 4; ng++)
                #pragma unroll
                for (int mf = 0; mf < 2; mf++) {
                    MMA16816(acc[mf][2 * ng],     ah[mf], bf[ng][0], bf[ng][1]);
                    MMA16816(acc[mf][2 * ng + 1], ah[mf], bf[ng][2], bf[ng][3]);
                }
            // pass 2: Alo * Bhi
            #pragma unroll
            for (int ng = 0; ng < 4; ng++)
                #pragma unroll
                for (int mf = 0; mf < 2; mf++) {
                    MMA16816(acc[mf][2 * ng],     al[mf], bf[ng][0], bf[ng][1]);
                    MMA16816(acc[mf][2 * ng + 1], al[mf], bf[ng][2], bf[ng][3]);
                }
            // load B lo (overwrite bf)
            #pragma unroll
            for (int ng = 0; ng < 4; ng++) {
                int row = rowB0 + ng * 16;
                uint32_t base = sB + (uint32_t)(row * 128);
                uint32_t sw = (uint32_t)((row & 7) << 4);
                uint32_t kh = (uint32_t)((ks * 16 + kbB) * 2);
                LDSM_X4(bf[ng], base + ((kh + 64) ^ sw));
            }
            // pass 3: Ahi * Blo
            #pragma unroll
            for (int ng = 0; ng < 4; ng++)
                #pragma unroll
                for (int mf = 0; mf < 2; mf++) {
                    MMA16816(acc[mf][2 * ng],     ah[mf], bf[ng][0], bf[ng][1]);
                    MMA16816(acc[mf][2 * ng + 1], ah[mf], bf[ng][2], bf[ng][3]);
                }
        }
    };

    load_stage(0, 0); CP_COMMIT();
    load_stage(1, 1); CP_COMMIT();
    for (int c = 0; c < NCH; c++) {
        CP_WAIT1();
        __syncthreads();
        if (c + 2 < NCH) load_stage(c + 2, (c + 2) % 3);
        CP_COMMIT();
        compute_stage(c % 3);
    }

    // ---------------- epilogue --------------------------------------------
    const float* bias = bias_all + (size_t)e * Nd;
    const int rbase = m0 + wm * 32 + (lane >> 2);
    const int cbase = n0 + wn * 64 + (lane & 3) * 2;

    #pragma unroll
    for (int mf = 0; mf < 2; mf++) {
        #pragma unroll
        for (int cp = 0; cp < 2; cp++) {
            int row = rbase + mf * 16 + cp * 8;
            if (row >= cnt) continue;
            if (LAYER == 1) {
                __nv_bfloat16* orow = g_A2 + ((size_t)e * EMAX + row) * (2 * HDIM);
                #pragma unroll
                for (int nf = 0; nf < 8; nf++) {
                    int col = cbase + nf * 8;
                    float v0 = gelu_exact(acc[mf][nf][2 * cp]     + bias[col]);
                    float v1 = gelu_exact(acc[mf][nf][2 * cp + 1] + bias[col + 1]);
                    int ch = col >> 5, pos = col & 31;
                    *(uint32_t*)&orow[ch * 64 + pos]      = pack_hi2(v0, v1);
                    *(uint32_t*)&orow[ch * 64 + pos + 32] = pack_lo2(v0, v1);
                }
            } else {
                int slot = g_slots[e * NTOK + row];
                float* orow = g_y + (size_t)slot * ODIM;
                #pragma unroll
                for (int nf = 0; nf < 8; nf++) {
                    int col = cbase + nf * 8;
                    float v0 = gelu_exact(acc[mf][nf][2 * cp]     + bias[col]);
                    float v1 = gelu_exact(acc[mf][nf][2 * cp + 1] + bias[col + 1]);
                    *(float2*)&orow[col] = make_float2(v0, v1);
                }
            }
        }
    }
}

// ---------------- kernel 6: combine + mask ---------------------------------
__global__ __launch_bounds__(256)
void combine_kernel(const float* __restrict__ mask, float* __restrict__ out)
{
    const int n = blockIdx.x;
    const int tid = threadIdx.x;
    const float m  = mask[n];
    const float p0 = g_prob[2 * n] * m;
    const float p1 = g_prob[2 * n + 1] * m;
    const float* y0 = g_y + (size_t)(2 * n) * ODIM;
    const float* y1 = y0 + ODIM;
    float* o = out + (size_t)n * ODIM;
    for (int c = tid; c < ODIM; c += 256)
        o[c] = p0 * y0[c] + p1 * y1[c];
}

// ---------------- launch ----------------------------------------------------
extern "C" void kernel_launch(void* const* d_in, const int* in_sizes, int n_in,
                              void* d_out, int out_size)
{
    const float* x     = (const float*)d_in[0];
    const float* mask  = (const float*)d_in[1];
    const float* gamma = (const float*)d_in[2];
    const float* beta  = (const float*)d_in[3];
    const float* rw    = (const float*)d_in[4];
    const float* w1    = (const float*)d_in[5];
    const float* b1    = (const float*)d_in[6];
    const float* w2    = (const float*)d_in[7];
    const float* b2    = (const float*)d_in[8];
    float* out = (float*)d_out;

    const int TBO = NTOK * ODIM;
    const int write_logits = (out_size >= TBO + NTOK * NEXP) ? 1 : 0;
    const int DSMEM = 98304;   // 3 stages x (16K A + 16K B)

    static int attr_done = 0;
    if (!attr_done) {
        cudaFuncSetAttribute(mma_gemm<1>, cudaFuncAttributeMaxDynamicSharedMemorySize, DSMEM);
        cudaFuncSetAttribute(mma_gemm<2>, cudaFuncAttributeMaxDynamicSharedMemorySize, DSMEM);
        attr_done = 1;
    }

    zero_kernel<<<1, 32>>>();
    ln_router_kernel<<<NTOK, 256>>>(x, gamma, beta, rw, out + TBO, write_logits);
    pack1_kernel<<<dim3(EMAX / 128, NEXP), 256>>>();
    wcvt_kernel<1><<<dim3(DDIM / 32, HDIM / 32, NEXP), 256>>>(w1);
    wcvt_kernel<2><<<dim3(HDIM / 32, ODIM / 32, NEXP), 256>>>(w2);
    mma_gemm<1><<<dim3(EMAX / 128, HDIM / 128, NEXP), 256, DSMEM>>>(b1);
    mma_gemm<2><<<dim3(EMAX / 128, ODIM / 128, NEXP), 256, DSMEM>>>(b2);
    combine_kernel<<<NTOK, 256>>>(mask, out);
}

// round 11
// speedup vs baseline: 5.6501x; 2.0319x over previous
#include <cuda_runtime.h>
#include <cuda_fp16.h>
#include <math.h>
#include <cstdint>

#define NTOK 4096      // T*B
#define DDIM 1024
#define HDIM 2048
#define ODIM 1024
#define NEXP 8
#define EMAX 4096      // max tokens per expert

// fp16 panels: A [E][EMAX][Kd] (row-major K), B [E][Nd][Kd] (N rows, K contig).

// ---------------- scratch (device globals; no allocation allowed) ----------
__device__ float g_xn[(size_t)NTOK * DDIM];                          // 16 MB
__device__ float g_y[(size_t)2 * NTOK * ODIM];                       // 32 MB
__device__ int   g_cnt[NEXP];
__device__ int   g_slots[NEXP * NTOK];
__device__ float g_prob[2 * NTOK];
__device__ __half g_A1[(size_t)NEXP * EMAX * DDIM];                  // 67 MB
__device__ __half g_A2[(size_t)NEXP * EMAX * HDIM];                  // 134 MB
__device__ __half g_B1[(size_t)NEXP * HDIM * DDIM];                  // 33.5 MB
__device__ __half g_B2[(size_t)NEXP * ODIM * HDIM];                  // 33.5 MB

// ---------------- PTX helpers ----------------------------------------------
__device__ __forceinline__ uint32_t smem_to_u32(const void* p) {
    uint32_t a;
    asm("{ .reg .u64 t; cvta.to.shared.u64 t, %1; cvt.u32.u64 %0, t; }" : "=r"(a) : "l"(p));
    return a;
}
#define CP_ASYNC16(saddr, gptr) \
    asm volatile("cp.async.cg.shared.global [%0], [%1], 16;" :: "r"(saddr), "l"(gptr))
#define CP_COMMIT() asm volatile("cp.async.commit_group;" ::: "memory")
#define CP_WAIT1()  asm volatile("cp.async.wait_group 1;" ::: "memory")
#define LDSM_X4(R, addr) \
    asm volatile("ldmatrix.sync.aligned.m8n8.x4.shared.b16 {%0,%1,%2,%3}, [%4];" \
                 : "=r"((R)[0]), "=r"((R)[1]), "=r"((R)[2]), "=r"((R)[3]) : "r"(addr))
#define MMAH16816(D, A, B0, B1) \
    asm volatile("mma.sync.aligned.m16n8k16.row.col.f32.f16.f16.f32 " \
        "{%0,%1,%2,%3}, {%4,%5,%6,%7}, {%8,%9}, {%0,%1,%2,%3};" \
        : "+f"((D)[0]), "+f"((D)[1]), "+f"((D)[2]), "+f"((D)[3]) \
        : "r"((A)[0]), "r"((A)[1]), "r"((A)[2]), "r"((A)[3]), "r"(B0), "r"(B1))

__device__ __forceinline__ float gelu_exact(float v) {
    return 0.5f * v * (1.0f + erff(v * 0.70710678118654752440f));
}
__device__ __forceinline__ uint32_t pack_h2(float a, float b) {
    __half2 h = __floats2half2_rn(a, b);
    return *(uint32_t*)&h;
}

// ---------------- kernel 0: zero counters ----------------------------------
__global__ void zero_kernel() {
    if (threadIdx.x < NEXP) g_cnt[threadIdx.x] = 0;
}

// ---------------- kernel 1: LN + router + top2 + scatter -------------------
__global__ __launch_bounds__(256)
void ln_router_kernel(const float* __restrict__ x,
                      const float* __restrict__ gamma,
                      const float* __restrict__ beta,
                      const float* __restrict__ rw,
                      float* __restrict__ logits_out,
                      int write_logits)
{
    const int n = blockIdx.x;
    const int tid = threadIdx.x;
    __shared__ float sx[DDIM];
    __shared__ float red[256];
    __shared__ float sstat[2];
    __shared__ float lg[NEXP];

    const float* xr = x + (size_t)n * DDIM;
    float s = 0.f;
    for (int i = tid; i < DDIM; i += 256) { float v = xr[i]; sx[i] = v; s += v; }
    red[tid] = s; __syncthreads();
    for (int st = 128; st > 0; st >>= 1) { if (tid < st) red[tid] += red[tid + st]; __syncthreads(); }
    if (tid == 0) sstat[0] = red[0] * (1.0f / DDIM);
    __syncthreads();
    const float mu = sstat[0];
    float s2 = 0.f;
    for (int i = tid; i < DDIM; i += 256) { float v = sx[i] - mu; s2 += v * v; }
    red[tid] = s2; __syncthreads();
    for (int st = 128; st > 0; st >>= 1) { if (tid < st) red[tid] += red[tid + st]; __syncthreads(); }
    if (tid == 0) sstat[1] = rsqrtf(red[0] * (1.0f / DDIM) + 1e-5f);
    __syncthreads();
    const float rstd = sstat[1];
    for (int i = tid; i < DDIM; i += 256) {
        float v = (sx[i] - mu) * rstd * gamma[i] + beta[i];
        sx[i] = v;
        g_xn[(size_t)n * DDIM + i] = v;
    }
    __syncthreads();

    const int w = tid >> 5, lane = tid & 31;
    {
        const float* r = rw + w * DDIM;
        float p = 0.f;
        for (int i = lane; i < DDIM; i += 32) p += sx[i] * r[i];
        #pragma unroll
        for (int o = 16; o > 0; o >>= 1) p += __shfl_down_sync(0xffffffffu, p, o);
        if (lane == 0) lg[w] = p;
    }
    __syncthreads();

    if (tid == 0) {
        if (write_logits) {
            #pragma unroll
            for (int e = 0; e < NEXP; e++) logits_out[(size_t)n * NEXP + e] = lg[e];
        }
        int i0 = 0;
        #pragma unroll
        for (int e = 1; e < NEXP; e++) if (lg[e] > lg[i0]) i0 = e;
        int i1 = (i0 == 0) ? 1 : 0;
        #pragma unroll
        for (int e = 0; e < NEXP; e++) if (e != i0 && lg[e] > lg[i1]) i1 = e;
        float q = expf(lg[i1] - lg[i0]);
        float inv = 1.0f / (1.0f + q);
        g_prob[2 * n]     = inv;
        g_prob[2 * n + 1] = q * inv;
        int p0 = atomicAdd(&g_cnt[i0], 1); g_slots[i0 * NTOK + p0] = 2 * n;
        int p1 = atomicAdd(&g_cnt[i1], 1); g_slots[i1 * NTOK + p1] = 2 * n + 1;
    }
}

// ---------------- kernel 2: pack tokens into per-expert A1 (fp16) ----------
__global__ __launch_bounds__(256)
void pack1_kernel()
{
    const int e = blockIdx.y;
    const int m0 = blockIdx.x * 128;
    const int cnt = g_cnt[e];
    if (m0 >= cnt) return;
    const int tid = threadIdx.x;
    __half* outp = g_A1 + ((size_t)e * EMAX) * DDIM;
    for (int idx = tid; idx < 128 * 256; idx += 256) {
        int r = idx >> 8;
        int c4 = idx & 255;
        int row = m0 + r;
        if (row >= cnt) continue;
        int token = g_slots[e * NTOK + row] >> 1;
        float4 v = ((const float4*)g_xn)[(size_t)token * 256 + c4];
        uint2 hp = make_uint2(pack_h2(v.x, v.y), pack_h2(v.z, v.w));
        *(uint2*)&outp[(size_t)row * DDIM + c4 * 4] = hp;
    }
}

// ---------------- kernel 3: weight transpose to fp16 -----------------------
// W [E][Kd][Nd] (fp32) -> B [E][Nd][Kd] (fp16)
template<int LAYER>
__global__ __launch_bounds__(256)
void wcvt_kernel(const float* __restrict__ W)
{
    constexpr int Kd = (LAYER == 1) ? DDIM : HDIM;
    constexpr int Nd = (LAYER == 1) ? HDIM : ODIM;
    __half* Bout = (LAYER == 1) ? g_B1 : g_B2;
    const int e = blockIdx.z;
    const int d0 = blockIdx.x * 32;   // K base
    const int h0 = blockIdx.y * 32;   // N base
    __shared__ float st[32][33];
    const int tid = threadIdx.x;
    {
        int dl = tid >> 3, q = tid & 7;
        float4 v = *(const float4*)(W + ((size_t)e * Kd + d0 + dl) * Nd + h0 + q * 4);
        st[dl][q * 4 + 0] = v.x; st[dl][q * 4 + 1] = v.y;
        st[dl][q * 4 + 2] = v.z; st[dl][q * 4 + 3] = v.w;
    }
    __syncthreads();
    const int n = tid >> 3, j0 = (tid & 7) * 4;
    uint2 pk = make_uint2(pack_h2(st[j0][n], st[j0 + 1][n]),
                          pack_h2(st[j0 + 2][n], st[j0 + 3][n]));
    *(uint2*)&Bout[((size_t)e * Nd + h0 + n) * Kd + d0 + j0] = pk;
}

// ---------------- kernels 4/5: grouped fp16 GEMM via mma.sync --------------
// Tile 128x128; K-chunk = 64 (one 128B row). 3-stage cp.async double buffer.
template<int LAYER>
__global__ __launch_bounds__(256, 2)
void mma_gemm(const float* __restrict__ bias_all)
{
    constexpr int Kd = (LAYER == 1) ? DDIM : HDIM;
    constexpr int Nd = (LAYER == 1) ? HDIM : ODIM;
    constexpr int NCH = Kd / 64;
    constexpr int STAGE_BYTES = 32768;   // A 16K + B 16K
    const __half* __restrict__ Aall = (LAYER == 1) ? g_A1 : g_A2;
    const __half* __restrict__ Ball = (LAYER == 1) ? g_B1 : g_B2;

    const int e = blockIdx.z;
    const int cnt = g_cnt[e];
    const int m0 = blockIdx.x * 128;
    if (m0 >= cnt) return;
    const int n0 = blockIdx.y * 128;

    extern __shared__ __align__(1024) char smem[];
    const uint32_t smem_u = smem_to_u32(smem);

    const int tid = threadIdx.x;
    const int lane = tid & 31;
    const int wid = tid >> 5;
    const int wm = wid >> 1;
    const int wn = wid & 1;

    const size_t rstride = Kd;   // elements
    const __half* Abase = Aall + ((size_t)e * EMAX + m0) * rstride;
    const __half* Bbase = Ball + ((size_t)e * Nd + n0) * rstride;

    const int lr = tid >> 3;          // 4 rows/thread, stride 32
    const int lch = tid & 7;          // 16B chunk in 128B row
    const uint32_t lsw = (uint32_t)(lch * 16) ^ (uint32_t)((lr & 7) << 4);

    float acc[2][8][4];
    #pragma unroll
    for (int i = 0; i < 2; i++)
        #pragma unroll
        for (int j = 0; j < 8; j++)
            #pragma unroll
            for (int q = 0; q < 4; q++) acc[i][j][q] = 0.f;

    auto load_stage = [&](int c, int st) {
        const int col = c * 64;       // element offset of 64-K chunk
        const uint32_t sA = smem_u + st * STAGE_BYTES;
        const uint32_t sB = sA + 16384;
        #pragma unroll
        for (int l = 0; l < 4; l++) {
            int r = lr + l * 32;
            CP_ASYNC16(sA + (uint32_t)(r * 128) + lsw,
                       (const char*)(Abase + (size_t)r * rstride + col) + lch * 16);
        }
        #pragma unroll
        for (int l = 0; l < 4; l++) {
            int r = lr + l * 32;
            CP_ASYNC16(sB + (uint32_t)(r * 128) + lsw,
                       (const char*)(Bbase + (size_t)r * rstride + col) + lch * 16);
        }
    };

    const int rowA0 = wm * 32 + (lane & 15);
    const int kbA = (lane >> 4) * 8;
    const int g = lane >> 3;
    const int rowB0 = wn * 64 + ((g >> 1) << 3) + (lane & 7);
    const int kbB = (g & 1) * 8;

    auto compute_stage = [&](int st) {
        const uint32_t sA = smem_u + st * STAGE_BYTES;
        const uint32_t sB = sA + 16384;
        #pragma unroll
        for (int ks = 0; ks < 4; ks++) {
            uint32_t af[2][4], bf[4][4];
            #pragma unroll
            for (int mf = 0; mf < 2; mf++) {
                int row = rowA0 + mf * 16;
                uint32_t koff = (uint32_t)((ks * 16 + kbA) * 2) ^ (uint32_t)((row & 7) << 4);
                LDSM_X4(af[mf], sA + (uint32_t)(row * 128) + koff);
            }
            #pragma unroll
            for (int ng = 0; ng < 4; ng++) {
                int row = rowB0 + ng * 16;
                uint32_t koff = (uint32_t)((ks * 16 + kbB) * 2) ^ (uint32_t)((row & 7) << 4);
                LDSM_X4(bf[ng], sB + (uint32_t)(row * 128) + koff);
            }
            #pragma unroll
            for (int ng = 0; ng < 4; ng++)
                #pragma unroll
                for (int mf = 0; mf < 2; mf++) {
                    MMAH16816(acc[mf][2 * ng],     af[mf], bf[ng][0], bf[ng][1]);
                    MMAH16816(acc[mf][2 * ng + 1], af[mf], bf[ng][2], bf[ng][3]);
                }
        }
    };

    load_stage(0, 0); CP_COMMIT();
    load_stage(1, 1); CP_COMMIT();
    for (int c = 0; c < NCH; c++) {
        CP_WAIT1();
        __syncthreads();
        if (c + 2 < NCH) load_stage(c + 2, (c + 2) % 3);
        CP_COMMIT();
        compute_stage(c % 3);
    }

    // ---------------- epilogue --------------------------------------------
    const float* bias = bias_all + (size_t)e * Nd;
    const int rbase = m0 + wm * 32 + (lane >> 2);
    const int cbase = n0 + wn * 64 + (lane & 3) * 2;

    #pragma unroll
    for (int mf = 0; mf < 2; mf++) {
        #pragma unroll
        for (int cp = 0; cp < 2; cp++) {
            int row = rbase + mf * 16 + cp * 8;
            if (row >= cnt) continue;
            if (LAYER == 1) {
                __half* orow = g_A2 + ((size_t)e * EMAX + row) * HDIM;
                #pragma unroll
                for (int nf = 0; nf < 8; nf++) {
                    int col = cbase + nf * 8;
                    float v0 = gelu_exact(acc[mf][nf][2 * cp]     + bias[col]);
                    float v1 = gelu_exact(acc[mf][nf][2 * cp + 1] + bias[col + 1]);
                    *(uint32_t*)&orow[col] = pack_h2(v0, v1);
                }
            } else {
                int slot = g_slots[e * NTOK + row];
                float* orow = g_y + (size_t)slot * ODIM;
                #pragma unroll
                for (int nf = 0; nf < 8; nf++) {
                    int col = cbase + nf * 8;
                    float v0 = gelu_exact(acc[mf][nf][2 * cp]     + bias[col]);
                    float v1 = gelu_exact(acc[mf][nf][2 * cp + 1] + bias[col + 1]);
                    *(float2*)&orow[col] = make_float2(v0, v1);
                }
            }
        }
    }
}

// ---------------- kernel 6: combine + mask ---------------------------------
__global__ __launch_bounds__(256)
void combine_kernel(const float* __restrict__ mask, float* __restrict__ out)
{
    const int n = blockIdx.x;
    const int tid = threadIdx.x;
    const float m  = mask[n];
    const float p0 = g_prob[2 * n] * m;
    const float p1 = g_prob[2 * n + 1] * m;
    const float* y0 = g_y + (size_t)(2 * n) * ODIM;
    const float* y1 = y0 + ODIM;
    float* o = out + (size_t)n * ODIM;
    for (int c = tid; c < ODIM; c += 256)
        o[c] = p0 * y0[c] + p1 * y1[c];
}

// ---------------- launch ----------------------------------------------------
extern "C" void kernel_launch(void* const* d_in, const int* in_sizes, int n_in,
                              void* d_out, int out_size)
{
    const float* x     = (const float*)d_in[0];
    const float* mask  = (const float*)d_in[1];
    const float* gamma = (const float*)d_in[2];
    const float* beta  = (const float*)d_in[3];
    const float* rw    = (const float*)d_in[4];
    const float* w1    = (const float*)d_in[5];
    const float* b1    = (const float*)d_in[6];
    const float* w2    = (const float*)d_in[7];
    const float* b2    = (const float*)d_in[8];
    float* out = (float*)d_out;

    const int TBO = NTOK * ODIM;
    const int write_logits = (out_size >= TBO + NTOK * NEXP) ? 1 : 0;
    const int DSMEM = 98304;   // 3 stages x (16K A + 16K B)

    static int attr_done = 0;
    if (!attr_done) {
        cudaFuncSetAttribute(mma_gemm<1>, cudaFuncAttributeMaxDynamicSharedMemorySize, DSMEM);
        cudaFuncSetAttribute(mma_gemm<2>, cudaFuncAttributeMaxDynamicSharedMemorySize, DSMEM);
        attr_done = 1;
    }

    zero_kernel<<<1, 32>>>();
    ln_router_kernel<<<NTOK, 256>>>(x, gamma, beta, rw, out + TBO, write_logits);
    pack1_kernel<<<dim3(EMAX / 128, NEXP), 256>>>();
    wcvt_kernel<1><<<dim3(DDIM / 32, HDIM / 32, NEXP), 256>>>(w1);
    wcvt_kernel<2><<<dim3(HDIM / 32, ODIM / 32, NEXP), 256>>>(w2);
    mma_gemm<1><<<dim3(EMAX / 128, HDIM / 128, NEXP), 256, DSMEM>>>(b1);
    mma_gemm<2><<<dim3(EMAX / 128, ODIM / 128, NEXP), 256, DSMEM>>>(b2);
    combine_kernel<<<NTOK, 256>>>(mask, out);
}